// round 1
// baseline (speedup 1.0000x reference)
#include <cuda_runtime.h>
#include <cstdint>
#include <cstddef>

// Problem dims
#define BB 16
#define TT 4096
#define DD 512
#define HH 512
#define NC 1536   // 3*H

// ---------------- scratch (device globals: no runtime allocation allowed) ---
__device__ float g_xk[(size_t)BB * TT * NC];   // 402 MB: x @ kernel + bias0
__device__ float g_hbuf[2][BB][HH];            // double-buffered hidden state
__device__ int   g_ctr[8 * TT];                // per-group per-step arrival counters

// ============================================================================
// Phase 1: xk[m][n] = sum_k x[m][k] * W[k][n] + bias0[n]
// M = B*T = 65536, K = 512, N = 1536.  Tile 128x128x16, 256 thr, 8x8 micro.
// ============================================================================
#define BM 128
#define BN 128
#define BK 16

__global__ void __launch_bounds__(256, 2)
gemm_xk_kernel(const float* __restrict__ A,
               const float* __restrict__ W,
               const float* __restrict__ bias)
{
    __shared__ float As[BK][BM];   // A tile transposed: As[k][m]
    __shared__ float Bs[BK][BN];   // Bs[k][n]

    const int bm  = blockIdx.y * BM;
    const int bn  = blockIdx.x * BN;
    const int tid = threadIdx.x;
    const int tx  = tid & 15;   // 16 col threads
    const int ty  = tid >> 4;   // 16 row threads

    float acc[8][8];
#pragma unroll
    for (int i = 0; i < 8; i++)
#pragma unroll
        for (int j = 0; j < 8; j++) acc[i][j] = 0.f;

    for (int kt = 0; kt < DD; kt += BK) {
        // Load A tile (128 x 16) as float4 along k, store transposed.
#pragma unroll
        for (int i = 0; i < 2; i++) {
            int idx = tid * 2 + i;          // 0..511
            int m   = idx >> 2;             // 0..127
            int k4  = (idx & 3) << 2;       // 0,4,8,12
            float4 v = *(const float4*)&A[(size_t)(bm + m) * DD + kt + k4];
            As[k4 + 0][m] = v.x;
            As[k4 + 1][m] = v.y;
            As[k4 + 2][m] = v.z;
            As[k4 + 3][m] = v.w;
        }
        // Load B tile (16 x 128) as float4 along n.
#pragma unroll
        for (int i = 0; i < 2; i++) {
            int idx = tid * 2 + i;          // 0..511
            int k   = idx >> 5;             // 0..15
            int n4  = (idx & 31) << 2;      // 0..124
            *(float4*)&Bs[k][n4] =
                *(const float4*)&W[(size_t)(kt + k) * NC + bn + n4];
        }
        __syncthreads();

#pragma unroll
        for (int k = 0; k < BK; k++) {
            float a[8], b[8];
#pragma unroll
            for (int i = 0; i < 8; i++) a[i] = As[k][ty * 8 + i];
#pragma unroll
            for (int j = 0; j < 8; j++) b[j] = Bs[k][tx * 8 + j];
#pragma unroll
            for (int i = 0; i < 8; i++)
#pragma unroll
                for (int j = 0; j < 8; j++) acc[i][j] += a[i] * b[j];
        }
        __syncthreads();
    }

    // Epilogue: add input bias (bias row 0), store to g_xk.
#pragma unroll
    for (int i = 0; i < 8; i++) {
        int m = bm + ty * 8 + i;
#pragma unroll
        for (int j = 0; j < 8; j += 4) {
            int n = bn + tx * 8 + j;
            float4 v;
            v.x = acc[i][j + 0] + bias[n + 0];
            v.y = acc[i][j + 1] + bias[n + 1];
            v.z = acc[i][j + 2] + bias[n + 2];
            v.w = acc[i][j + 3] + bias[n + 3];
            *(float4*)&g_xk[(size_t)m * NC + n] = v;
        }
    }
}

// ============================================================================
// Phase 2: persistent GRU recurrence.
//   128 CTAs = 8 groups x 16 CTAs. Group g owns batches {2g, 2g+1}.
//   CTA c of a group owns units j in [32c, 32c+32); holds U columns
//   {j, 512+j, 1024+j} in SMEM as U_s[gate*32+u][k], row stride 513
//   (conflict-free: bank = (row+k) % 32).
//   Per step: rec slice via 256 threads = 32 unit-threads x 8 K-splits,
//   smem reduction, gate math by 64 threads, publish h_new slice to global,
//   counter barrier among the 16 CTAs, reload full h.
// ============================================================================
#define USTRIDE 513
#define SM_FLOATS (96 * USTRIDE + 1024 + 8 * 192 + 96)

__global__ void __launch_bounds__(256, 1)
gru_rec_kernel(const float* __restrict__ RK,
               const float* __restrict__ bias,
               float* __restrict__ out)
{
    extern __shared__ float sm[];
    float* U_s  = sm;                        // [96][513]
    float* h_s  = U_s + 96 * USTRIDE;        // [2][512]
    float* red  = h_s + 1024;                // [8][32][6]
    float* rb_s = red + 8 * 192;             // [96] recurrent bias slice

    const int bx  = blockIdx.x;
    const int g   = bx >> 4;                 // group 0..7
    const int c   = bx & 15;                 // cta-in-group 0..15
    const int tid = threadIdx.x;
    const int jb  = c * 32;                  // first unit owned
    const int b0  = g * 2;                   // first global batch

    // ---- Load U slice (coalesced over columns per k-row) -------------------
    for (int idx = tid; idx < 512 * 96; idx += 256) {
        int k    = idx / 96;
        int col  = idx - k * 96;             // col = gate*32 + u
        int gate = col >> 5;
        int u    = col & 31;
        U_s[col * USTRIDE + k] = RK[(size_t)k * NC + gate * HH + jb + u];
    }
    if (tid < 96) {
        int gate = tid >> 5, u = tid & 31;
        rb_s[tid] = bias[NC + gate * HH + jb + u];   // bias row 1 = recurrent
    }
    for (int i = tid; i < 1024; i += 256) h_s[i] = 0.f;   // h0 = zeros
    __syncthreads();

    const int ct = tid & 31;                 // unit thread
    const int ks = tid >> 5;                 // K split 0..7
    const float* uz  = U_s + ct * USTRIDE + ks * 64;
    const float* ur  = uz + 32 * USTRIDE;
    const float* uh  = uz + 64 * USTRIDE;
    const float* hp0 = h_s + ks * 64;
    const float* hp1 = h_s + 512 + ks * 64;

    const int gb_b = tid >> 5;               // gate-phase batch (valid tid<64)
    const int gb_u = tid & 31;               // gate-phase unit
    int* ctr = &g_ctr[g * TT];

    for (int t = 0; t < TT; t++) {
        // Prefetch this step's xk values early (overlap with the dot loop).
        float xz = 0.f, xr = 0.f, xh = 0.f;
        if (tid < 64) {
            size_t base = ((size_t)(b0 + gb_b) * TT + t) * NC + jb + gb_u;
            xz = g_xk[base];
            xr = g_xk[base + HH];
            xh = g_xk[base + 2 * HH];
        }

        // ---- rec slice: 6 dot-partials per thread over a 64-wide K chunk ---
        float a00 = 0.f, a01 = 0.f, a02 = 0.f, a10 = 0.f, a11 = 0.f, a12 = 0.f;
#pragma unroll 8
        for (int k = 0; k < 64; k++) {
            float h0 = hp0[k], h1 = hp1[k];
            float wz = uz[k], wr = ur[k], wh = uh[k];
            a00 += h0 * wz; a01 += h0 * wr; a02 += h0 * wh;
            a10 += h1 * wz; a11 += h1 * wr; a12 += h1 * wh;
        }
        float* rp = red + ks * 192 + ct * 6;
        rp[0] = a00; rp[1] = a01; rp[2] = a02;
        rp[3] = a10; rp[4] = a11; rp[5] = a12;
        __syncthreads();

        // ---- reduce + gates + publish (64 threads: 2 batches x 32 units) ---
        if (tid < 64) {
            float sz = 0.f, sr = 0.f, sh = 0.f;
#pragma unroll
            for (int q = 0; q < 8; q++) {
                const float* qp = red + q * 192 + gb_u * 6 + gb_b * 3;
                sz += qp[0]; sr += qp[1]; sh += qp[2];
            }
            sz += rb_s[gb_u];
            sr += rb_s[32 + gb_u];
            sh += rb_s[64 + gb_u];

            float z    = 1.f / (1.f + __expf(-(xz + sz)));
            float r    = 1.f / (1.f + __expf(-(xr + sr)));
            float cand = tanhf(xh + r * sh);
            float hold = h_s[gb_b * HH + jb + gb_u];
            float hn   = z * hold + (1.f - z) * cand;

            int gb = b0 + gb_b;
            out[((size_t)gb * TT + t) * HH + jb + gb_u] = hn;
            if (t == TT - 1)
                out[(size_t)BB * TT * HH + (size_t)gb * HH + jb + gb_u] = hn;
            g_hbuf[(t + 1) & 1][gb][jb + gb_u] = hn;
            __threadfence();   // make slice visible before the arrival below
        }
        __syncthreads();

        // ---- group barrier: per-step counter (no reset race, memset/launch)
        if (tid == 0) {
            atomicAdd(&ctr[t], 1);
            while (*(volatile int*)&ctr[t] != 16) { }
            __threadfence();
        }
        __syncthreads();

        // ---- reload full h for our 2 batches -------------------------------
        {
            const float* src = &g_hbuf[(t + 1) & 1][b0][0];
            for (int i = tid; i < 1024; i += 256) h_s[i] = src[i];
        }
        __syncthreads();
    }
}

// ============================================================================
extern "C" void kernel_launch(void* const* d_in, const int* in_sizes, int n_in,
                              void* d_out, int out_size)
{
    const float* x    = (const float*)d_in[0];   // [16,4096,512]
    const float* Wk   = (const float*)d_in[1];   // [512,1536]
    const float* RK   = (const float*)d_in[2];   // [512,1536]
    const float* bias = (const float*)d_in[3];   // [2,1536]
    float* out = (float*)d_out;                  // outputs ++ state

    // Zero the barrier counters (captured as a memset node; re-zeroed per replay).
    void* ctr_ptr = nullptr;
    cudaGetSymbolAddress(&ctr_ptr, g_ctr);
    cudaMemsetAsync(ctr_ptr, 0, sizeof(int) * 8 * TT);

    // Phase 1: input projection GEMM.
    dim3 grid1(NC / BN, (BB * TT) / BM);
    gemm_xk_kernel<<<grid1, 256>>>(x, Wk, bias);

    // Phase 2: persistent recurrence (opt-in to >48KB dynamic smem).
    const size_t smem_bytes = (size_t)SM_FLOATS * sizeof(float);  // ~208 KB
    cudaFuncSetAttribute(gru_rec_kernel,
                         cudaFuncAttributeMaxDynamicSharedMemorySize,
                         (int)smem_bytes);
    gru_rec_kernel<<<128, 256, smem_bytes>>>(RK, bias, out);
}

// round 2
// speedup vs baseline: 1.3062x; 1.3062x over previous
#include <cuda_runtime.h>
#include <cstdint>
#include <cstddef>

// Problem dims
#define BB 16
#define TT 4096
#define DD 512
#define HH 512
#define NC 1536   // 3*H

typedef unsigned long long ull;

// ---------------- scratch (device globals: no runtime allocation allowed) ---
__device__ float g_xk[(size_t)BB * TT * NC];   // 402 MB: x @ kernel + bias0
__device__ float g_hbuf[2][BB][HH];            // double-buffered hidden state
__device__ int   g_ctr[8 * TT];                // per-group per-step arrival counters

// ---------------- f32x2 packed-math helpers (sm_103a) -----------------------
__device__ __forceinline__ ull pk2(float lo, float hi) {
    ull r;
    asm("mov.b64 %0, {%1, %2};" : "=l"(r) : "f"(lo), "f"(hi));
    return r;
}
__device__ __forceinline__ void unpk2(float& lo, float& hi, ull v) {
    asm("mov.b64 {%0, %1}, %2;" : "=f"(lo), "=f"(hi) : "l"(v));
}
__device__ __forceinline__ ull fma2(ull a, ull b, ull c) {
    ull d;
    asm("fma.rn.f32x2 %0, %1, %2, %3;" : "=l"(d) : "l"(a), "l"(b), "l"(c));
    return d;
}
__device__ __forceinline__ float sigmoid_f(float x) {
    return 1.f / (1.f + __expf(-x));
}
__device__ __forceinline__ float tanh_f(float x) {
    float e = __expf(2.f * x);
    return (e - 1.f) / (e + 1.f);
}

// ============================================================================
// Phase 1: xk[m][n] = sum_k x[m][k] * W[k][n] + bias0[n]
// M = B*T = 65536, K = 512, N = 1536.  Tile 128x128x16, 256 thr, 8x8 micro,
// inner product via packed fma.rn.f32x2 (accumulator pairs along n).
// ============================================================================
#define BM 128
#define BN 128
#define BK 16

__global__ void __launch_bounds__(256, 2)
gemm_xk_kernel(const float* __restrict__ A,
               const float* __restrict__ W,
               const float* __restrict__ bias)
{
    __shared__ float As[BK][BM];   // A tile transposed: As[k][m]
    __shared__ float Bs[BK][BN];   // Bs[k][n]

    const int bm  = blockIdx.y * BM;
    const int bn  = blockIdx.x * BN;
    const int tid = threadIdx.x;
    const int tx  = tid & 15;   // 16 col threads
    const int ty  = tid >> 4;   // 16 row threads

    ull accp[8][4];
#pragma unroll
    for (int i = 0; i < 8; i++)
#pragma unroll
        for (int j = 0; j < 4; j++) accp[i][j] = 0ull;

    for (int kt = 0; kt < DD; kt += BK) {
        // Load A tile (128 x 16) as float4 along k, store transposed.
#pragma unroll
        for (int i = 0; i < 2; i++) {
            int idx = tid * 2 + i;          // 0..511
            int m   = idx >> 2;             // 0..127
            int k4  = (idx & 3) << 2;       // 0,4,8,12
            float4 v = *(const float4*)&A[(size_t)(bm + m) * DD + kt + k4];
            As[k4 + 0][m] = v.x;
            As[k4 + 1][m] = v.y;
            As[k4 + 2][m] = v.z;
            As[k4 + 3][m] = v.w;
        }
        // Load B tile (16 x 128) as float4 along n.
#pragma unroll
        for (int i = 0; i < 2; i++) {
            int idx = tid * 2 + i;          // 0..511
            int k   = idx >> 5;             // 0..15
            int n4  = (idx & 31) << 2;      // 0..124
            *(float4*)&Bs[k][n4] =
                *(const float4*)&W[(size_t)(kt + k) * NC + bn + n4];
        }
        __syncthreads();

#pragma unroll
        for (int k = 0; k < BK; k++) {
            float4 av0 = *(const float4*)&As[k][ty * 8];
            float4 av1 = *(const float4*)&As[k][ty * 8 + 4];
            ulonglong2 bv0 = *(const ulonglong2*)&Bs[k][tx * 8];
            ulonglong2 bv1 = *(const ulonglong2*)&Bs[k][tx * 8 + 4];
            ull bp0 = bv0.x, bp1 = bv0.y, bp2 = bv1.x, bp3 = bv1.y;
            float a[8] = {av0.x, av0.y, av0.z, av0.w,
                          av1.x, av1.y, av1.z, av1.w};
#pragma unroll
            for (int i = 0; i < 8; i++) {
                ull ap = pk2(a[i], a[i]);
                accp[i][0] = fma2(ap, bp0, accp[i][0]);
                accp[i][1] = fma2(ap, bp1, accp[i][1]);
                accp[i][2] = fma2(ap, bp2, accp[i][2]);
                accp[i][3] = fma2(ap, bp3, accp[i][3]);
            }
        }
        __syncthreads();
    }

    // Epilogue: unpack, add input bias (bias row 0), store to g_xk.
#pragma unroll
    for (int i = 0; i < 8; i++) {
        int m = bm + ty * 8 + i;
#pragma unroll
        for (int jp = 0; jp < 2; jp++) {   // two float4 stores of 4 cols each
            int n = bn + tx * 8 + jp * 4;
            float l0, h0, l1, h1;
            unpk2(l0, h0, accp[i][jp * 2 + 0]);
            unpk2(l1, h1, accp[i][jp * 2 + 1]);
            float4 v;
            v.x = l0 + bias[n + 0];
            v.y = h0 + bias[n + 1];
            v.z = l1 + bias[n + 2];
            v.w = h1 + bias[n + 3];
            *(float4*)&g_xk[(size_t)m * NC + n] = v;
        }
    }
}

// ============================================================================
// Phase 2: persistent GRU recurrence — U in REGISTERS, packed f32x2 math.
//   128 CTAs = 8 groups x 16 CTAs. Group g owns batches {2g, 2g+1}.
//   CTA c owns units [32c, 32c+32). 512 threads: thread (u = lane, ks = warp)
//   holds U[k0..k0+32) for its unit's 3 gate columns as 48 packed f32x2 regs.
//   Per step: h read as broadcast LDS.64 (lanes in a warp share k), 6 packed
//   FFMA2 per k-pair; smem tree reduction over the 16 K-split warps; 64
//   threads do gate math + publish; per-step global counter barrier; reload h.
// ============================================================================
__global__ void __launch_bounds__(512, 1)
gru_rec_kernel(const float* __restrict__ RK,
               const float* __restrict__ bias,
               float* __restrict__ out)
{
    __shared__ float h_s[2 * HH];          // [batch][k]
    __shared__ float red[16][32][7];       // [ks][u][gate*2+b], pad 7 -> no cfl
    __shared__ float rb_s[96];             // recurrent bias slice

    const int bx  = blockIdx.x;
    const int g   = bx >> 4;               // group 0..7
    const int c   = bx & 15;               // cta-in-group 0..15
    const int tid = threadIdx.x;
    const int u   = tid & 31;              // unit within slice
    const int ks  = tid >> 5;              // K-split warp 0..15
    const int jb  = c * 32;                // first unit owned
    const int b0  = g * 2;                 // first global batch
    const int k0  = ks * 32;               // this thread's K chunk

    // ---- Load U slice into registers (coalesced: lanes = consecutive cols) -
    ull ureg[3][16];
#pragma unroll
    for (int gi = 0; gi < 3; gi++)
#pragma unroll
        for (int i = 0; i < 16; i++) {
            int k = k0 + 2 * i;
            float lo = RK[(size_t)k       * NC + gi * HH + jb + u];
            float hi = RK[(size_t)(k + 1) * NC + gi * HH + jb + u];
            ureg[gi][i] = pk2(lo, hi);
        }
    if (tid < 96)
        rb_s[tid] = bias[NC + (tid >> 5) * HH + jb + (tid & 31)];
    for (int i = tid; i < 2 * HH; i += 512) h_s[i] = 0.f;   // h0 = zeros
    __syncthreads();

    const int gb_b = tid >> 5;             // gate-phase batch  (valid tid<64)
    const int gb_u = tid & 31;             // gate-phase unit
    int* ctr = &g_ctr[g * TT];

    for (int t = 0; t < TT; t++) {
        // Prefetch this step's xk values (long-scoreboard covered by the dot).
        float xz = 0.f, xr = 0.f, xh = 0.f;
        if (tid < 64) {
            size_t base = ((size_t)(b0 + gb_b) * TT + t) * NC + jb + gb_u;
            xz = g_xk[base];
            xr = g_xk[base + HH];
            xh = g_xk[base + 2 * HH];
        }

        // ---- packed dot: 6 f32x2 accumulators over a 32-wide K chunk -------
        const ull* hp0 = (const ull*)&h_s[k0];
        const ull* hp1 = (const ull*)&h_s[HH + k0];
        ull a0 = 0, a1 = 0, a2 = 0, a3 = 0, a4 = 0, a5 = 0;
#pragma unroll
        for (int i = 0; i < 16; i++) {
            ull h0 = hp0[i];               // broadcast LDS.64 (warp-uniform)
            ull h1 = hp1[i];
            a0 = fma2(ureg[0][i], h0, a0);
            a1 = fma2(ureg[1][i], h0, a1);
            a2 = fma2(ureg[2][i], h0, a2);
            a3 = fma2(ureg[0][i], h1, a3);
            a4 = fma2(ureg[1][i], h1, a4);
            a5 = fma2(ureg[2][i], h1, a5);
        }
        // horizontal add + stash partials: red[ks][u][gate*2 + b]
        {
            float lo, hi;
            unpk2(lo, hi, a0); red[ks][u][0] = lo + hi;   // z, b0
            unpk2(lo, hi, a1); red[ks][u][2] = lo + hi;   // r, b0
            unpk2(lo, hi, a2); red[ks][u][4] = lo + hi;   // h, b0
            unpk2(lo, hi, a3); red[ks][u][1] = lo + hi;   // z, b1
            unpk2(lo, hi, a4); red[ks][u][3] = lo + hi;   // r, b1
            unpk2(lo, hi, a5); red[ks][u][5] = lo + hi;   // h, b1
        }
        __syncthreads();

        // ---- reduce over 16 K-splits + gates + publish (64 threads) --------
        if (tid < 64) {
            float s0 = 0.f, s1 = 0.f, s2 = 0.f;
#pragma unroll
            for (int q = 0; q < 16; q++) {
                s0 += red[q][gb_u][0 + gb_b];
                s1 += red[q][gb_u][2 + gb_b];
                s2 += red[q][gb_u][4 + gb_b];
            }
            s0 += rb_s[gb_u];
            s1 += rb_s[32 + gb_u];
            s2 += rb_s[64 + gb_u];

            float z    = sigmoid_f(xz + s0);
            float r    = sigmoid_f(xr + s1);
            float cand = tanh_f(xh + r * s2);
            float hold = h_s[gb_b * HH + jb + gb_u];
            float hn   = z * hold + (1.f - z) * cand;

            int gb = b0 + gb_b;
            out[((size_t)gb * TT + t) * HH + jb + gb_u] = hn;
            if (t == TT - 1)
                out[(size_t)BB * TT * HH + (size_t)gb * HH + jb + gb_u] = hn;
            g_hbuf[(t + 1) & 1][gb][jb + gb_u] = hn;
            __threadfence();   // slice visible before the arrival below
        }
        __syncthreads();

        // ---- group barrier: per-step counter -------------------------------
        if (tid == 0) {
            atomicAdd(&ctr[t], 1);
            while (*(volatile int*)&ctr[t] != 16) { }
            __threadfence();
        }
        __syncthreads();

        // ---- reload full h for our 2 batches -------------------------------
        {
            const float* src = &g_hbuf[(t + 1) & 1][b0][0];
            for (int i = tid; i < 2 * HH; i += 512) h_s[i] = src[i];
        }
        __syncthreads();
    }
}

// ============================================================================
extern "C" void kernel_launch(void* const* d_in, const int* in_sizes, int n_in,
                              void* d_out, int out_size)
{
    const float* x    = (const float*)d_in[0];   // [16,4096,512]
    const float* Wk   = (const float*)d_in[1];   // [512,1536]
    const float* RK   = (const float*)d_in[2];   // [512,1536]
    const float* bias = (const float*)d_in[3];   // [2,1536]
    float* out = (float*)d_out;                  // outputs ++ state

    // Zero the barrier counters (memset node; re-zeroed per graph replay).
    void* ctr_ptr = nullptr;
    cudaGetSymbolAddress(&ctr_ptr, g_ctr);
    cudaMemsetAsync(ctr_ptr, 0, sizeof(int) * 8 * TT);

    // Phase 1: input projection GEMM.
    dim3 grid1(NC / BN, (BB * TT) / BM);
    gemm_xk_kernel<<<grid1, 256>>>(x, Wk, bias);

    // Phase 2: persistent recurrence.
    gru_rec_kernel<<<128, 512>>>(RK, bias, out);
}